// round 1
// baseline (speedup 1.0000x reference)
#include <cuda_runtime.h>
#include <cuda_bf16.h>
#include <math_constants.h>

// Problem constants
#define NROWS 16384
#define NA    256
#define NF    2048
#define NFTOT (NROWS * NF)
#define GAMMA 1.5f
#define BN_EPS 1e-5f

// ---------------- scratch (allocation-free: __device__ globals) ----------------
__device__ float g_X[NROWS * NF];        // 128 MB: GEMM output x = a @ W^T
__device__ float g_psum[64 * NF];        // partial column sums
__device__ float g_psq[64 * NF];         // partial column sum-squares
__device__ float g_scale[NF];            // bn_w * rstd
__device__ float g_shift[NF];            // bn_b - mean * scale

// ================================================================
// K1: GEMM  x[m][f] = sum_k a[m][k] * W[f][k]
// (bias b omitted: BatchNorm subtracts the column mean, so any
//  per-feature constant shift cancels exactly.)
// Tiles: 128x128x16, 256 threads, 8x8 per-thread microtile.
// ================================================================
#define BM 128
#define BN 128
#define BK 16
#define LDT 132   // padded smem row stride (floats), 16B-aligned

__global__ void __launch_bounds__(256)
gemm_kernel(const float* __restrict__ A, const float* __restrict__ W)
{
    __shared__ float As[BK][LDT];
    __shared__ float Ws[BK][LDT];

    const int tid = threadIdx.x;
    const int m0 = blockIdx.y * BM;
    const int f0 = blockIdx.x * BN;

    const int rg = (tid >> 4) * 8;    // row group within tile
    const int cg = (tid & 15) * 8;    // col group within tile

    float acc[8][8];
#pragma unroll
    for (int i = 0; i < 8; i++)
#pragma unroll
        for (int j = 0; j < 8; j++) acc[i][j] = 0.0f;

    for (int kc = 0; kc < NA; kc += BK) {
        // cooperative load: 128x16 of A and 128x16 of W, transposed into smem
#pragma unroll
        for (int t = tid; t < 512; t += 256) {
            const int r  = t >> 2;
            const int c4 = (t & 3) * 4;
            float4 av = *(const float4*)&A[(m0 + r) * NA + kc + c4];
            As[c4 + 0][r] = av.x; As[c4 + 1][r] = av.y;
            As[c4 + 2][r] = av.z; As[c4 + 3][r] = av.w;
            float4 wv = *(const float4*)&W[(f0 + r) * NA + kc + c4];
            Ws[c4 + 0][r] = wv.x; Ws[c4 + 1][r] = wv.y;
            Ws[c4 + 2][r] = wv.z; Ws[c4 + 3][r] = wv.w;
        }
        __syncthreads();

#pragma unroll
        for (int kk = 0; kk < BK; kk++) {
            float4 a0 = *(const float4*)&As[kk][rg];
            float4 a1 = *(const float4*)&As[kk][rg + 4];
            float4 b0 = *(const float4*)&Ws[kk][cg];
            float4 b1 = *(const float4*)&Ws[kk][cg + 4];
            float af[8] = {a0.x, a0.y, a0.z, a0.w, a1.x, a1.y, a1.z, a1.w};
            float bf[8] = {b0.x, b0.y, b0.z, b0.w, b1.x, b1.y, b1.z, b1.w};
#pragma unroll
            for (int i = 0; i < 8; i++)
#pragma unroll
                for (int j = 0; j < 8; j++)
                    acc[i][j] = fmaf(af[i], bf[j], acc[i][j]);
        }
        __syncthreads();
    }

    // store
#pragma unroll
    for (int i = 0; i < 8; i++) {
        float* xp = &g_X[(m0 + rg + i) * NF + f0 + cg];
        float4 v0 = make_float4(acc[i][0], acc[i][1], acc[i][2], acc[i][3]);
        float4 v1 = make_float4(acc[i][4], acc[i][5], acc[i][6], acc[i][7]);
        *(float4*)(xp)     = v0;
        *(float4*)(xp + 4) = v1;
    }
}

// ================================================================
// K2: per-(row-chunk, feature) partial sums / sumsq
// grid (8, 64), block 256: feature = bx*256+tx, rows = by*256..+256
// ================================================================
__global__ void __launch_bounds__(256)
colstats_kernel()
{
    const int f = blockIdx.x * 256 + threadIdx.x;
    const int row0 = blockIdx.y * 256;
    float s = 0.0f, q = 0.0f;
#pragma unroll 4
    for (int r = 0; r < 256; r++) {
        float v = g_X[(row0 + r) * NF + f];
        s += v;
        q = fmaf(v, v, q);
    }
    g_psum[blockIdx.y * NF + f] = s;
    g_psq [blockIdx.y * NF + f] = q;
}

// ================================================================
// K3: finalize column stats -> scale/shift
// ================================================================
__global__ void __launch_bounds__(256)
finalize_kernel(const float* __restrict__ bn_w, const float* __restrict__ bn_b)
{
    const int f = blockIdx.x * 256 + threadIdx.x;
    float s = 0.0f, q = 0.0f;
#pragma unroll
    for (int c = 0; c < 64; c++) {
        s += g_psum[c * NF + f];
        q += g_psq [c * NF + f];
    }
    const float inv_n = 1.0f / (float)NROWS;
    float mean = s * inv_n;
    float var  = fmaxf(q * inv_n - mean * mean, 0.0f);
    float rstd = rsqrtf(var + BN_EPS);
    float sc = bn_w[f] * rstd;
    g_scale[f] = sc;
    g_shift[f] = bn_b[f] - mean * sc;
}

// ================================================================
// K4: per-row sparsemax + outputs. One block (256 threads) per row.
// Fast path: if 1 + 2047*max(z) - sum(z) > 0 (the reference's
// ascending-sort condition at the last index), then k_z = 2047,
// support = all elements, tau = (sum(z)+1)/2047. This condition
// holds for any non-degenerate row (sum <= D*max). A full bitonic
// fallback implements the exact reference algorithm otherwise.
// ================================================================
__device__ __forceinline__ float block_reduce(float v, float* buf, bool do_max)
{
    const unsigned FULL = 0xffffffffu;
#pragma unroll
    for (int o = 16; o > 0; o >>= 1) {
        float t = __shfl_down_sync(FULL, v, o);
        v = do_max ? fmaxf(v, t) : (v + t);
    }
    const int w = threadIdx.x >> 5, l = threadIdx.x & 31;
    if (l == 0) buf[w] = v;
    __syncthreads();
    if (threadIdx.x < 8) {
        v = buf[threadIdx.x];
#pragma unroll
        for (int o = 4; o > 0; o >>= 1) {
            float t = __shfl_down_sync(0xffu, v, o);
            v = do_max ? fmaxf(v, t) : (v + t);
        }
        if (threadIdx.x == 0) buf[0] = v;
    }
    __syncthreads();
    float r = buf[0];
    __syncthreads();
    return r;
}

__global__ void __launch_bounds__(256)
row_kernel(const float* __restrict__ ps, float* __restrict__ out)
{
    __shared__ float s_a[NF];   // fallback sort buffer
    __shared__ float s_b[NF];   // fallback scan buffer
    __shared__ float rbuf[8];

    const int row = blockIdx.x;
    const int tid = threadIdx.x;

    const float4* xp  = (const float4*)(g_X + (size_t)row * NF);
    const float4* pp  = (const float4*)(ps  + (size_t)row * NF);
    const float4* scp = (const float4*)g_scale;
    const float4* shp = (const float4*)g_shift;

    float z[8], pv8[8];
    float S = 0.0f, mx = -CUDART_INF_F;

#pragma unroll
    for (int g = 0; g < 2; g++) {
        const int q = tid + g * 256;
        float4 xv = xp[q], pv = pp[q], sc = scp[q], sh = shp[q];
        float z0 = fmaf(xv.x, sc.x, sh.x) * pv.x;
        float z1 = fmaf(xv.y, sc.y, sh.y) * pv.y;
        float z2 = fmaf(xv.z, sc.z, sh.z) * pv.z;
        float z3 = fmaf(xv.w, sc.w, sh.w) * pv.w;
        z[g*4+0]=z0; z[g*4+1]=z1; z[g*4+2]=z2; z[g*4+3]=z3;
        pv8[g*4+0]=pv.x; pv8[g*4+1]=pv.y; pv8[g*4+2]=pv.z; pv8[g*4+3]=pv.w;
        S += (z0 + z1) + (z2 + z3);
        mx = fmaxf(mx, fmaxf(fmaxf(z0, z1), fmaxf(z2, z3)));
    }

    S  = block_reduce(S,  rbuf, false);
    mx = block_reduce(mx, rbuf, true);

    float tau;
    if (1.0f + 2047.0f * mx - S > 0.0f) {
        // fast path: k_z = D-1, support is all elements
        tau = (S + 1.0f) * (1.0f / 2047.0f);
    } else {
        // ---- exact fallback: ascending bitonic sort + scan (rarely taken) ----
#pragma unroll
        for (int g = 0; g < 2; g++)
#pragma unroll
            for (int j = 0; j < 4; j++)
                s_a[(tid + g * 256) * 4 + j] = z[g * 4 + j];
        __syncthreads();

        for (int k = 2; k <= NF; k <<= 1) {
            for (int j = k >> 1; j > 0; j >>= 1) {
                for (int i = tid; i < NF; i += 256) {
                    int ixj = i ^ j;
                    if (ixj > i) {
                        bool up = ((i & k) == 0);
                        float va = s_a[i], vb = s_a[ixj];
                        if ((va > vb) == up) { s_a[i] = vb; s_a[ixj] = va; }
                    }
                }
                __syncthreads();
            }
        }
        // stash sorted values this thread owns
        float sv[8];
#pragma unroll
        for (int e = 0; e < 8; e++) sv[e] = s_a[tid + e * 256];
        // inclusive scan (Hillis-Steele, ping-pong)
        float* src = s_a;
        float* dst = s_b;
        for (int off = 1; off < NF; off <<= 1) {
            for (int i = tid; i < NF; i += 256)
                dst[i] = src[i] + ((i >= off) ? src[i - off] : 0.0f);
            __syncthreads();
            float* t = src; src = dst; dst = t;
        }
        // condition per sorted index; k = max index where it holds
        float kf = 0.0f;
#pragma unroll
        for (int e = 0; e < 8; e++) {
            int i = tid + e * 256;
            if (1.0f + (float)i * sv[e] - src[i] > 0.0f) kf = fmaxf(kf, (float)i);
        }
        kf = block_reduce(kf, rbuf, true);
        int k = (int)kf;
        tau = (src[k] + 1.0f) / (float)k;
        __syncthreads();
    }

    // outputs: m and new_ps = ps * (GAMMA - m)
    float* om = out + (size_t)row * NF;
    float* op = out + (size_t)NFTOT + (size_t)row * NF;
#pragma unroll
    for (int g = 0; g < 2; g++) {
        const int q = tid + g * 256;
        float m0 = fmaxf(z[g*4+0] - tau, 0.0f);
        float m1 = fmaxf(z[g*4+1] - tau, 0.0f);
        float m2 = fmaxf(z[g*4+2] - tau, 0.0f);
        float m3 = fmaxf(z[g*4+3] - tau, 0.0f);
        ((float4*)om)[q] = make_float4(m0, m1, m2, m3);
        ((float4*)op)[q] = make_float4(pv8[g*4+0] * (GAMMA - m0),
                                       pv8[g*4+1] * (GAMMA - m1),
                                       pv8[g*4+2] * (GAMMA - m2),
                                       pv8[g*4+3] * (GAMMA - m3));
    }
}

// ================================================================
// launch
// inputs (metadata order): a, ps, W, b, bn_w, bn_b
// output: concat(m, new_ps) -> 2*N*F floats
// ================================================================
extern "C" void kernel_launch(void* const* d_in, const int* in_sizes, int n_in,
                              void* d_out, int out_size)
{
    const float* a    = (const float*)d_in[0];
    const float* ps   = (const float*)d_in[1];
    const float* W    = (const float*)d_in[2];
    // d_in[3] = b : provably cancelled by BatchNorm mean subtraction
    const float* bn_w = (const float*)d_in[4];
    const float* bn_b = (const float*)d_in[5];
    float* out = (float*)d_out;

    gemm_kernel<<<dim3(NF / BN, NROWS / BM), 256>>>(a, W);
    colstats_kernel<<<dim3(NF / 256, 64), 256>>>();
    finalize_kernel<<<NF / 256, 256>>>(bn_w, bn_b);
    row_kernel<<<NROWS, 256>>>(ps, out);
}

// round 3
// speedup vs baseline: 1.9150x; 1.9150x over previous
#include <cuda_runtime.h>
#include <cuda_bf16.h>
#include <math_constants.h>
#include <cstdint>

// Problem constants
#define NROWS 16384
#define NA    256
#define NF    2048
#define NFTOT (NROWS * NF)
#define GAMMA 1.5f
#define BN_EPS 1e-5f

#define KCAT  768           // 3 * NA (bf16x3 split concatenated along K)
#define BK    32            // K per pipeline stage
#define NKIT  (KCAT / BK)   // 24
#define NSTG  4
#define STG_BYTES 16384     // A 8KB + B 8KB

// ---------------- scratch (allocation-free: __device__ globals) ----------------
__device__ float         g_X[NROWS * NF];              // GEMM output (fp32)
__device__ __nv_bfloat16 g_Acat[(size_t)NROWS * KCAT]; // [Ah | Al | Ah]
__device__ __nv_bfloat16 g_Wcat[(size_t)NF * KCAT];    // [Wh | Wh | Wl]
__device__ float         g_colsum[NF];
__device__ float         g_colsq[NF];
__device__ float         g_scale[NF];
__device__ float         g_shift[NF];

// ================= PTX helpers (baseline ISA only: valid on sm_103) =================
__device__ __forceinline__ uint32_t smem_u32(const void* p) {
    uint32_t a;
    asm("{ .reg .u64 t; cvta.to.shared.u64 t, %1; cvt.u32.u64 %0, t; }" : "=r"(a) : "l"(p));
    return a;
}
__device__ __forceinline__ void cp16(uint32_t sm, const void* g) {
    asm volatile("cp.async.cg.shared.global [%0], [%1], 16;" :: "r"(sm),
                 "l"(__cvta_generic_to_global(g)));
}
#define CP_COMMIT() asm volatile("cp.async.commit_group;" ::: "memory")
#define CP_WAIT(n)  asm volatile("cp.async.wait_group %0;" :: "n"(n) : "memory")

__device__ __forceinline__ void ldsm_x4(uint32_t& r0, uint32_t& r1, uint32_t& r2,
                                        uint32_t& r3, uint32_t addr) {
    asm volatile("ldmatrix.sync.aligned.m8n8.x4.shared.b16 {%0,%1,%2,%3}, [%4];"
        : "=r"(r0), "=r"(r1), "=r"(r2), "=r"(r3) : "r"(addr));
}
__device__ __forceinline__ void mma16816(float* d, const uint32_t* a,
                                         uint32_t b0, uint32_t b1) {
    asm volatile("mma.sync.aligned.m16n8k16.row.col.f32.bf16.bf16.f32 "
        "{%0,%1,%2,%3}, {%4,%5,%6,%7}, {%8,%9}, {%0,%1,%2,%3};"
        : "+f"(d[0]), "+f"(d[1]), "+f"(d[2]), "+f"(d[3])
        : "r"(a[0]), "r"(a[1]), "r"(a[2]), "r"(a[3]), "r"(b0), "r"(b1));
}

// ================================================================
// K0: zero stats accumulators
// ================================================================
__global__ void zero_stats_kernel() {
    int i = blockIdx.x * 256 + threadIdx.x;
    if (i < NF) { g_colsum[i] = 0.0f; g_colsq[i] = 0.0f; }
}

// ================================================================
// K1a/K1b: bf16x3 split + concat along K.
//   A_cat @ W_cat^T = Ah Wh + Al Wh + Ah Wl  (misses only Al Wl ~ 2^-18)
// (bias b omitted: cancelled exactly by BatchNorm mean subtraction)
// ================================================================
__global__ void __launch_bounds__(256) convA_kernel(const float* __restrict__ a) {
    int idx = blockIdx.x * 256 + threadIdx.x;
    float v = a[idx];
    __nv_bfloat16 hi = __float2bfloat16(v);
    __nv_bfloat16 lo = __float2bfloat16(v - __bfloat162float(hi));
    int row = idx >> 8, k = idx & 255;
    size_t base = (size_t)row * KCAT;
    g_Acat[base + k]       = hi;
    g_Acat[base + 256 + k] = lo;
    g_Acat[base + 512 + k] = hi;
}
__global__ void __launch_bounds__(256) convW_kernel(const float* __restrict__ W) {
    int idx = blockIdx.x * 256 + threadIdx.x;
    float v = W[idx];
    __nv_bfloat16 hi = __float2bfloat16(v);
    __nv_bfloat16 lo = __float2bfloat16(v - __bfloat162float(hi));
    int row = idx >> 8, k = idx & 255;
    size_t base = (size_t)row * KCAT;
    g_Wcat[base + k]       = hi;
    g_Wcat[base + 256 + k] = hi;
    g_Wcat[base + 512 + k] = lo;
}

// ================================================================
// K2: HMMA GEMM (mma.sync m16n8k16 bf16). CTA 128x128, 8 warps
// (4M x 2N), warp tile 32x64. 4-stage cp.async pipeline, BK=32.
// Epilogue: store g_X + fused column sum/sumsq via atomics.
// smem row = 32 bf16 = 4 x 16B segs, swizzle seg ^= (row>>1)&3
// -> conflict-free ldmatrix.x4 and conflict-free cp.async stores.
// ================================================================
__device__ __forceinline__ void load_stage(uint32_t sb, int slot, int it,
                                           int m0, int f0, int tid) {
    const int kc = it * BK;
    const uint32_t s = sb + slot * STG_BYTES;
#pragma unroll
    for (int j = 0; j < 2; j++) {
        int idx = tid + j * 256;
        int r = idx >> 2, seg = idx & 3;
        uint32_t sw = (uint32_t)((seg ^ ((r >> 1) & 3)) << 4);
        cp16(s + r * 64 + sw,
             (const char*)(g_Acat + (size_t)(m0 + r) * KCAT + kc) + seg * 16);
        cp16(s + 8192 + r * 64 + sw,
             (const char*)(g_Wcat + (size_t)(f0 + r) * KCAT + kc) + seg * 16);
    }
}

__global__ void __launch_bounds__(256, 2)
gemm_hmma_kernel() {
    extern __shared__ char smem[];
    const uint32_t sb = smem_u32(smem);
    const int tid = threadIdx.x;
    const int wid = tid >> 5, lid = tid & 31;
    const int warpM = wid & 3, warpN = wid >> 2;
    const int m0 = blockIdx.y * 128;
    const int f0 = blockIdx.x * 128;

    float acc[2][8][4];
#pragma unroll
    for (int t = 0; t < 2; t++)
#pragma unroll
        for (int j = 0; j < 8; j++)
#pragma unroll
            for (int e = 0; e < 4; e++) acc[t][j][e] = 0.0f;

    // prologue: 3 stages in flight
    load_stage(sb, 0, 0, m0, f0, tid); CP_COMMIT();
    load_stage(sb, 1, 1, m0, f0, tid); CP_COMMIT();
    load_stage(sb, 2, 2, m0, f0, tid); CP_COMMIT();

    for (int it = 0; it < NKIT; it++) {
        CP_WAIT(2);
        __syncthreads();
        if (it + 3 < NKIT) load_stage(sb, (it + 3) & 3, it + 3, m0, f0, tid);
        CP_COMMIT();

        const uint32_t s = sb + (it & 3) * STG_BYTES;
#pragma unroll
        for (int ks = 0; ks < 2; ks++) {
            uint32_t af[2][4], bf[4][4];
            const int segb = (lid >> 4) + ks * 2;
#pragma unroll
            for (int t = 0; t < 2; t++) {
                int r = warpM * 32 + t * 16 + (lid & 15);
                uint32_t addr = s + r * 64 + ((segb ^ ((r >> 1) & 3)) << 4);
                ldsm_x4(af[t][0], af[t][1], af[t][2], af[t][3], addr);
            }
#pragma unroll
            for (int u = 0; u < 4; u++) {
                int r = warpN * 64 + u * 16 + (lid & 15);
                uint32_t addr = s + 8192 + r * 64 + ((segb ^ ((r >> 1) & 3)) << 4);
                ldsm_x4(bf[u][0], bf[u][1], bf[u][2], bf[u][3], addr);
            }
#pragma unroll
            for (int t = 0; t < 2; t++)
#pragma unroll
                for (int u = 0; u < 4; u++) {
                    mma16816(acc[t][2 * u],     af[t], bf[u][0], bf[u][2]);
                    mma16816(acc[t][2 * u + 1], af[t], bf[u][1], bf[u][3]);
                }
        }
    }

    // epilogue: C -> g_X (v2 stores) + fused column stats
#pragma unroll
    for (int t = 0; t < 2; t++) {
        const int rbase = m0 + warpM * 32 + t * 16 + (lid >> 2);
#pragma unroll
        for (int j = 0; j < 8; j++) {
            const int col = f0 + warpN * 64 + j * 8 + (lid & 3) * 2;
            *(float2*)&g_X[(size_t)rbase * NF + col] =
                make_float2(acc[t][j][0], acc[t][j][1]);
            *(float2*)&g_X[(size_t)(rbase + 8) * NF + col] =
                make_float2(acc[t][j][2], acc[t][j][3]);
        }
    }
    const unsigned FULL = 0xffffffffu;
#pragma unroll
    for (int j = 0; j < 8; j++) {
        float s0 = acc[0][j][0] + acc[0][j][2] + acc[1][j][0] + acc[1][j][2];
        float s1 = acc[0][j][1] + acc[0][j][3] + acc[1][j][1] + acc[1][j][3];
        float q0 = acc[0][j][0]*acc[0][j][0] + acc[0][j][2]*acc[0][j][2]
                 + acc[1][j][0]*acc[1][j][0] + acc[1][j][2]*acc[1][j][2];
        float q1 = acc[0][j][1]*acc[0][j][1] + acc[0][j][3]*acc[0][j][3]
                 + acc[1][j][1]*acc[1][j][1] + acc[1][j][3]*acc[1][j][3];
#pragma unroll
        for (int o = 16; o >= 4; o >>= 1) {
            s0 += __shfl_down_sync(FULL, s0, o);
            s1 += __shfl_down_sync(FULL, s1, o);
            q0 += __shfl_down_sync(FULL, q0, o);
            q1 += __shfl_down_sync(FULL, q1, o);
        }
        if (lid < 4) {
            const int col = f0 + warpN * 64 + j * 8 + lid * 2;
            atomicAdd(&g_colsum[col], s0);
            atomicAdd(&g_colsum[col + 1], s1);
            atomicAdd(&g_colsq[col], q0);
            atomicAdd(&g_colsq[col + 1], q1);
        }
    }
}

// ================================================================
// K3: finalize column stats -> scale/shift
// ================================================================
__global__ void __launch_bounds__(256)
finalize_kernel(const float* __restrict__ bn_w, const float* __restrict__ bn_b) {
    const int f = blockIdx.x * 256 + threadIdx.x;
    const float inv_n = 1.0f / (float)NROWS;
    float mean = g_colsum[f] * inv_n;
    float var  = fmaxf(g_colsq[f] * inv_n - mean * mean, 0.0f);
    float rstd = rsqrtf(var + BN_EPS);
    float sc = bn_w[f] * rstd;
    g_scale[f] = sc;
    g_shift[f] = bn_b[f] - mean * sc;
}

// ================================================================
// K4: per-row sparsemax + outputs (HBM-roofline bound).
// ================================================================
__device__ __forceinline__ float block_reduce(float v, float* buf, bool do_max) {
    const unsigned FULL = 0xffffffffu;
#pragma unroll
    for (int o = 16; o > 0; o >>= 1) {
        float t = __shfl_down_sync(FULL, v, o);
        v = do_max ? fmaxf(v, t) : (v + t);
    }
    const int w = threadIdx.x >> 5, l = threadIdx.x & 31;
    if (l == 0) buf[w] = v;
    __syncthreads();
    if (threadIdx.x < 8) {
        v = buf[threadIdx.x];
#pragma unroll
        for (int o = 4; o > 0; o >>= 1) {
            float t = __shfl_down_sync(0xffu, v, o);
            v = do_max ? fmaxf(v, t) : (v + t);
        }
        if (threadIdx.x == 0) buf[0] = v;
    }
    __syncthreads();
    float r = buf[0];
    __syncthreads();
    return r;
}

__global__ void __launch_bounds__(256)
row_kernel(const float* __restrict__ ps, float* __restrict__ out) {
    __shared__ float s_a[NF];
    __shared__ float s_b[NF];
    __shared__ float rbuf[8];

    const int row = blockIdx.x;
    const int tid = threadIdx.x;

    const float4* xp  = (const float4*)(g_X + (size_t)row * NF);
    const float4* pp  = (const float4*)(ps  + (size_t)row * NF);
    const float4* scp = (const float4*)g_scale;
    const float4* shp = (const float4*)g_shift;

    float z[8], pv8[8];
    float S = 0.0f, mx = -CUDART_INF_F;

#pragma unroll
    for (int g = 0; g < 2; g++) {
        const int q = tid + g * 256;
        float4 xv = xp[q], pv = pp[q], sc = scp[q], sh = shp[q];
        float z0 = fmaf(xv.x, sc.x, sh.x) * pv.x;
        float z1 = fmaf(xv.y, sc.y, sh.y) * pv.y;
        float z2 = fmaf(xv.z, sc.z, sh.z) * pv.z;
        float z3 = fmaf(xv.w, sc.w, sh.w) * pv.w;
        z[g*4+0]=z0; z[g*4+1]=z1; z[g*4+2]=z2; z[g*4+3]=z3;
        pv8[g*4+0]=pv.x; pv8[g*4+1]=pv.y; pv8[g*4+2]=pv.z; pv8[g*4+3]=pv.w;
        S += (z0 + z1) + (z2 + z3);
        mx = fmaxf(mx, fmaxf(fmaxf(z0, z1), fmaxf(z2, z3)));
    }

    S  = block_reduce(S,  rbuf, false);
    mx = block_reduce(mx, rbuf, true);

    float tau;
    if (1.0f + 2047.0f * mx - S > 0.0f) {
        tau = (S + 1.0f) * (1.0f / 2047.0f);
    } else {
        // exact fallback (ascending bitonic sort + scan) — effectively never taken
#pragma unroll
        for (int g = 0; g < 2; g++)
#pragma unroll
            for (int j = 0; j < 4; j++)
                s_a[(tid + g * 256) * 4 + j] = z[g * 4 + j];
        __syncthreads();
        for (int k = 2; k <= NF; k <<= 1)
            for (int j = k >> 1; j > 0; j >>= 1) {
                for (int i = tid; i < NF; i += 256) {
                    int ixj = i ^ j;
                    if (ixj > i) {
                        bool up = ((i & k) == 0);
                        float va = s_a[i], vb = s_a[ixj];
                        if ((va > vb) == up) { s_a[i] = vb; s_a[ixj] = va; }
                    }
                }
                __syncthreads();
            }
        float sv[8];
#pragma unroll
        for (int e = 0; e < 8; e++) sv[e] = s_a[tid + e * 256];
        float* src = s_a; float* dst = s_b;
        for (int off = 1; off < NF; off <<= 1) {
            for (int i = tid; i < NF; i += 256)
                dst[i] = src[i] + ((i >= off) ? src[i - off] : 0.0f);
            __syncthreads();
            float* t = src; src = dst; dst = t;
        }
        float kf = 0.0f;
#pragma unroll
        for (int e = 0; e < 8; e++) {
            int i = tid + e * 256;
            if (1.0f + (float)i * sv[e] - src[i] > 0.0f) kf = fmaxf(kf, (float)i);
        }
        kf = block_reduce(kf, rbuf, true);
        int k = (int)kf;
        tau = (src[k] + 1.0f) / (float)k;
        __syncthreads();
    }

    float* om = out + (size_t)row * NF;
    float* op = out + (size_t)NFTOT + (size_t)row * NF;
#pragma unroll
    for (int g = 0; g < 2; g++) {
        const int q = tid + g * 256;
        float m0 = fmaxf(z[g*4+0] - tau, 0.0f);
        float m1 = fmaxf(z[g*4+1] - tau, 0.0f);
        float m2 = fmaxf(z[g*4+2] - tau, 0.0f);
        float m3 = fmaxf(z[g*4+3] - tau, 0.0f);
        ((float4*)om)[q] = make_float4(m0, m1, m2, m3);
        ((float4*)op)[q] = make_float4(pv8[g*4+0] * (GAMMA - m0),
                                       pv8[g*4+1] * (GAMMA - m1),
                                       pv8[g*4+2] * (GAMMA - m2),
                                       pv8[g*4+3] * (GAMMA - m3));
    }
}

// ================================================================
// launch: a, ps, W, b, bn_w, bn_b -> out = concat(m, new_ps)
// ================================================================
extern "C" void kernel_launch(void* const* d_in, const int* in_sizes, int n_in,
                              void* d_out, int out_size) {
    const float* a    = (const float*)d_in[0];
    const float* ps   = (const float*)d_in[1];
    const float* W    = (const float*)d_in[2];
    const float* bn_w = (const float*)d_in[4];
    const float* bn_b = (const float*)d_in[5];
    float* out = (float*)d_out;

    cudaFuncSetAttribute(gemm_hmma_kernel,
                         cudaFuncAttributeMaxDynamicSharedMemorySize,
                         NSTG * STG_BYTES);

    zero_stats_kernel<<<(NF + 255) / 256, 256>>>();
    convA_kernel<<<NROWS * NA / 256, 256>>>(a);
    convW_kernel<<<NF * NA / 256, 256>>>(W);
    gemm_hmma_kernel<<<dim3(NF / 128, NROWS / 128), 256, NSTG * STG_BYTES>>>();
    finalize_kernel<<<NF / 256, 256>>>(bn_w, bn_b);
    row_kernel<<<NROWS, 256>>>(ps, out);
}

// round 4
// speedup vs baseline: 2.4311x; 1.2695x over previous
#include <cuda_runtime.h>
#include <cuda_fp16.h>
#include <math_constants.h>
#include <cstdint>

// Problem constants
#define NROWS 16384
#define NA    256
#define NF    2048
#define NFTOT (NROWS * NF)
#define GAMMA 1.5f
#define BN_EPS 1e-5f

#define KCAT  512           // 2 * NA (fp16x2 split of A concatenated along K)
#define BK    32            // K per pipeline stage
#define NKIT  (KCAT / BK)   // 16
#define NSTG  4
#define STG_BYTES 16384     // A 8KB + B 8KB

// ---------------- scratch (allocation-free: __device__ globals) ----------------
__device__ float  g_X[NROWS * NF];               // GEMM output (fp32)
__device__ __half g_Acat[(size_t)NROWS * KCAT];  // [Ah | Al]
__device__ __half g_Wcat[(size_t)NF * KCAT];     // [Wh | Wh]
__device__ float  g_colsum[NF];
__device__ float  g_colsq[NF];
__device__ float  g_scale[NF];
__device__ float  g_shift[NF];

// ================= PTX helpers (baseline ISA only: valid on sm_103) =================
__device__ __forceinline__ uint32_t smem_u32(const void* p) {
    uint32_t a;
    asm("{ .reg .u64 t; cvta.to.shared.u64 t, %1; cvt.u32.u64 %0, t; }" : "=r"(a) : "l"(p));
    return a;
}
__device__ __forceinline__ void cp16(uint32_t sm, const void* g) {
    asm volatile("cp.async.cg.shared.global [%0], [%1], 16;" :: "r"(sm),
                 "l"(__cvta_generic_to_global(g)));
}
#define CP_COMMIT() asm volatile("cp.async.commit_group;" ::: "memory")
#define CP_WAIT(n)  asm volatile("cp.async.wait_group %0;" :: "n"(n) : "memory")

__device__ __forceinline__ void ldsm_x4(uint32_t& r0, uint32_t& r1, uint32_t& r2,
                                        uint32_t& r3, uint32_t addr) {
    asm volatile("ldmatrix.sync.aligned.m8n8.x4.shared.b16 {%0,%1,%2,%3}, [%4];"
        : "=r"(r0), "=r"(r1), "=r"(r2), "=r"(r3) : "r"(addr));
}
__device__ __forceinline__ void mma16816(float* d, const uint32_t* a,
                                         uint32_t b0, uint32_t b1) {
    asm volatile("mma.sync.aligned.m16n8k16.row.col.f32.f16.f16.f32 "
        "{%0,%1,%2,%3}, {%4,%5,%6,%7}, {%8,%9}, {%0,%1,%2,%3};"
        : "+f"(d[0]), "+f"(d[1]), "+f"(d[2]), "+f"(d[3])
        : "r"(a[0]), "r"(a[1]), "r"(a[2]), "r"(a[3]), "r"(b0), "r"(b1));
}

// ================================================================
// K0: zero stats accumulators
// ================================================================
__global__ void zero_stats_kernel() {
    int i = blockIdx.x * 256 + threadIdx.x;
    if (i < NF) { g_colsum[i] = 0.0f; g_colsq[i] = 0.0f; }
}

// ================================================================
// K1a/K1b: fp16x2 split of A, single fp16 of W, concat along K.
//   [Ah|Al] @ [Wh|Wh]^T = (Ah+Al) @ Wh^T = A @ Wh^T  (exact in A)
//   dropped term A@Wl^T : |Wl| <= 2^-11 |W|  ->  rel err ~3e-4 << 1e-3
// (bias b omitted: cancelled exactly by BatchNorm mean subtraction)
// ================================================================
__global__ void __launch_bounds__(256) convA_kernel(const float* __restrict__ a) {
    int idx = blockIdx.x * 256 + threadIdx.x;
    float v = a[idx];
    __half hi = __float2half(v);
    __half lo = __float2half(v - __half2float(hi));
    int row = idx >> 8, k = idx & 255;
    size_t base = (size_t)row * KCAT;
    g_Acat[base + k]       = hi;
    g_Acat[base + 256 + k] = lo;
}
__global__ void __launch_bounds__(256) convW_kernel(const float* __restrict__ W) {
    int idx = blockIdx.x * 256 + threadIdx.x;
    __half hi = __float2half(W[idx]);
    int row = idx >> 8, k = idx & 255;
    size_t base = (size_t)row * KCAT;
    g_Wcat[base + k]       = hi;
    g_Wcat[base + 256 + k] = hi;
}

// ================================================================
// K2: HMMA GEMM (mma.sync m16n8k16 fp16). CTA 128x128, 8 warps
// (4M x 2N), warp tile 32x64. 4-stage cp.async pipeline, BK=32.
// All smem addresses (swizzled) hoisted into registers; iteration
// loop unrolled x4 so stage offsets are compile-time constants.
// Epilogue: store g_X + fused column sum/sumsq via atomics.
// ================================================================
__global__ void __launch_bounds__(256, 2)
gemm_hmma_kernel() {
    extern __shared__ char smem[];
    const uint32_t sb = smem_u32(smem);
    const int tid = threadIdx.x;
    const int wid = tid >> 5, lid = tid & 31;
    const int warpM = wid & 3, warpN = wid >> 2;
    const int m0 = blockIdx.y * 128;
    const int f0 = blockIdx.x * 128;

    // ---- hoisted cp.async addresses (per thread: 2 A rows + 2 B rows) ----
    const int seg = tid & 3;
    const int r0 = tid >> 2, r1 = r0 + 64;
    const uint32_t swA0 = (uint32_t)r0 * 64u + (uint32_t)((seg ^ ((r0 >> 1) & 3)) << 4);
    const uint32_t swA1 = (uint32_t)r1 * 64u + (uint32_t)((seg ^ ((r1 >> 1) & 3)) << 4);
    const uint32_t sA0 = sb + swA0,        sA1 = sb + swA1;
    const uint32_t sB0 = sb + 8192 + swA0, sB1 = sb + 8192 + swA1;
    const char* gA0 = (const char*)(g_Acat + (size_t)(m0 + r0) * KCAT) + seg * 16;
    const char* gA1 = (const char*)(g_Acat + (size_t)(m0 + r1) * KCAT) + seg * 16;
    const char* gB0 = (const char*)(g_Wcat + (size_t)(f0 + r0) * KCAT) + seg * 16;
    const char* gB1 = (const char*)(g_Wcat + (size_t)(f0 + r1) * KCAT) + seg * 16;

    // ---- hoisted ldmatrix addresses (12 per thread) ----
    uint32_t adA[2][2], adB[4][2];
#pragma unroll
    for (int ks = 0; ks < 2; ks++) {
        const int segb = (lid >> 4) + ks * 2;
#pragma unroll
        for (int t = 0; t < 2; t++) {
            int r = warpM * 32 + t * 16 + (lid & 15);
            adA[t][ks] = sb + (uint32_t)r * 64u
                       + (uint32_t)((segb ^ ((r >> 1) & 3)) << 4);
        }
#pragma unroll
        for (int u = 0; u < 4; u++) {
            int r = warpN * 64 + u * 16 + (lid & 15);
            adB[u][ks] = sb + 8192u + (uint32_t)r * 64u
                       + (uint32_t)((segb ^ ((r >> 1) & 3)) << 4);
        }
    }

    float acc[2][8][4];
#pragma unroll
    for (int t = 0; t < 2; t++)
#pragma unroll
        for (int j = 0; j < 8; j++)
#pragma unroll
            for (int e = 0; e < 4; e++) acc[t][j][e] = 0.0f;

    // prologue: 3 stages in flight (stage i holds iteration i)
#pragma unroll
    for (int p = 0; p < 3; p++) {
        const uint32_t so = p * STG_BYTES;
        cp16(sA0 + so, gA0 + p * 64); cp16(sB0 + so, gB0 + p * 64);
        cp16(sA1 + so, gA1 + p * 64); cp16(sB1 + so, gB1 + p * 64);
        CP_COMMIT();
    }

#pragma unroll 1
    for (int it4 = 0; it4 < NKIT; it4 += 4) {
#pragma unroll
        for (int ii = 0; ii < 4; ii++) {
            const int it = it4 + ii;
            CP_WAIT(2);
            __syncthreads();
            if (it + 3 < NKIT) {
                const uint32_t so = ((ii + 3) & 3) * STG_BYTES;
                const int off = (it + 3) * 64;
                cp16(sA0 + so, gA0 + off); cp16(sB0 + so, gB0 + off);
                cp16(sA1 + so, gA1 + off); cp16(sB1 + so, gB1 + off);
            }
            CP_COMMIT();

            const uint32_t so = ii * STG_BYTES;   // compile-time constant
#pragma unroll
            for (int ks = 0; ks < 2; ks++) {
                uint32_t af[2][4], bf[4][4];
#pragma unroll
                for (int t = 0; t < 2; t++)
                    ldsm_x4(af[t][0], af[t][1], af[t][2], af[t][3], adA[t][ks] + so);
#pragma unroll
                for (int u = 0; u < 4; u++)
                    ldsm_x4(bf[u][0], bf[u][1], bf[u][2], bf[u][3], adB[u][ks] + so);
#pragma unroll
                for (int t = 0; t < 2; t++)
#pragma unroll
                    for (int u = 0; u < 4; u++) {
                        mma16816(acc[t][2 * u],     af[t], bf[u][0], bf[u][2]);
                        mma16816(acc[t][2 * u + 1], af[t], bf[u][1], bf[u][3]);
                    }
            }
        }
    }

    // epilogue: C -> g_X (v2 stores) + fused column stats
#pragma unroll
    for (int t = 0; t < 2; t++) {
        const int rbase = m0 + warpM * 32 + t * 16 + (lid >> 2);
#pragma unroll
        for (int j = 0; j < 8; j++) {
            const int col = f0 + warpN * 64 + j * 8 + (lid & 3) * 2;
            *(float2*)&g_X[(size_t)rbase * NF + col] =
                make_float2(acc[t][j][0], acc[t][j][1]);
            *(float2*)&g_X[(size_t)(rbase + 8) * NF + col] =
                make_float2(acc[t][j][2], acc[t][j][3]);
        }
    }
    const unsigned FULL = 0xffffffffu;
#pragma unroll
    for (int j = 0; j < 8; j++) {
        float s0 = acc[0][j][0] + acc[0][j][2] + acc[1][j][0] + acc[1][j][2];
        float s1 = acc[0][j][1] + acc[0][j][3] + acc[1][j][1] + acc[1][j][3];
        float q0 = acc[0][j][0]*acc[0][j][0] + acc[0][j][2]*acc[0][j][2]
                 + acc[1][j][0]*acc[1][j][0] + acc[1][j][2]*acc[1][j][2];
        float q1 = acc[0][j][1]*acc[0][j][1] + acc[0][j][3]*acc[0][j][3]
                 + acc[1][j][1]*acc[1][j][1] + acc[1][j][3]*acc[1][j][3];
#pragma unroll
        for (int o = 16; o >= 4; o >>= 1) {
            s0 += __shfl_down_sync(FULL, s0, o);
            s1 += __shfl_down_sync(FULL, s1, o);
            q0 += __shfl_down_sync(FULL, q0, o);
            q1 += __shfl_down_sync(FULL, q1, o);
        }
        if (lid < 4) {
            const int col = f0 + warpN * 64 + j * 8 + lid * 2;
            atomicAdd(&g_colsum[col], s0);
            atomicAdd(&g_colsum[col + 1], s1);
            atomicAdd(&g_colsq[col], q0);
            atomicAdd(&g_colsq[col + 1], q1);
        }
    }
}

// ================================================================
// K3: finalize column stats -> scale/shift
// ================================================================
__global__ void __launch_bounds__(256)
finalize_kernel(const float* __restrict__ bn_w, const float* __restrict__ bn_b) {
    const int f = blockIdx.x * 256 + threadIdx.x;
    const float inv_n = 1.0f / (float)NROWS;
    float mean = g_colsum[f] * inv_n;
    float var  = fmaxf(g_colsq[f] * inv_n - mean * mean, 0.0f);
    float rstd = rsqrtf(var + BN_EPS);
    float sc = bn_w[f] * rstd;
    g_scale[f] = sc;
    g_shift[f] = bn_b[f] - mean * sc;
}

// ================================================================
// K4: per-row sparsemax + outputs (HBM-roofline bound).
// ================================================================
__device__ __forceinline__ float block_reduce(float v, float* buf, bool do_max) {
    const unsigned FULL = 0xffffffffu;
#pragma unroll
    for (int o = 16; o > 0; o >>= 1) {
        float t = __shfl_down_sync(FULL, v, o);
        v = do_max ? fmaxf(v, t) : (v + t);
    }
    const int w = threadIdx.x >> 5, l = threadIdx.x & 31;
    if (l == 0) buf[w] = v;
    __syncthreads();
    if (threadIdx.x < 8) {
        v = buf[threadIdx.x];
#pragma unroll
        for (int o = 4; o > 0; o >>= 1) {
            float t = __shfl_down_sync(0xffu, v, o);
            v = do_max ? fmaxf(v, t) : (v + t);
        }
        if (threadIdx.x == 0) buf[0] = v;
    }
    __syncthreads();
    float r = buf[0];
    __syncthreads();
    return r;
}

__global__ void __launch_bounds__(256)
row_kernel(const float* __restrict__ ps, float* __restrict__ out) {
    __shared__ float s_a[NF];
    __shared__ float s_b[NF];
    __shared__ float rbuf[8];

    const int row = blockIdx.x;
    const int tid = threadIdx.x;

    const float4* xp  = (const float4*)(g_X + (size_t)row * NF);
    const float4* pp  = (const float4*)(ps  + (size_t)row * NF);
    const float4* scp = (const float4*)g_scale;
    const float4* shp = (const float4*)g_shift;

    float z[8], pv8[8];
    float S = 0.0f, mx = -CUDART_INF_F;

#pragma unroll
    for (int g = 0; g < 2; g++) {
        const int q = tid + g * 256;
        float4 xv = xp[q], pv = pp[q], sc = scp[q], sh = shp[q];
        float z0 = fmaf(xv.x, sc.x, sh.x) * pv.x;
        float z1 = fmaf(xv.y, sc.y, sh.y) * pv.y;
        float z2 = fmaf(xv.z, sc.z, sh.z) * pv.z;
        float z3 = fmaf(xv.w, sc.w, sh.w) * pv.w;
        z[g*4+0]=z0; z[g*4+1]=z1; z[g*4+2]=z2; z[g*4+3]=z3;
        pv8[g*4+0]=pv.x; pv8[g*4+1]=pv.y; pv8[g*4+2]=pv.z; pv8[g*4+3]=pv.w;
        S += (z0 + z1) + (z2 + z3);
        mx = fmaxf(mx, fmaxf(fmaxf(z0, z1), fmaxf(z2, z3)));
    }

    S  = block_reduce(S,  rbuf, false);
    mx = block_reduce(mx, rbuf, true);

    float tau;
    if (1.0f + 2047.0f * mx - S > 0.0f) {
        tau = (S + 1.0f) * (1.0f / 2047.0f);
    } else {
        // exact fallback (ascending bitonic sort + scan) — effectively never taken
#pragma unroll
        for (int g = 0; g < 2; g++)
#pragma unroll
            for (int j = 0; j < 4; j++)
                s_a[(tid + g * 256) * 4 + j] = z[g * 4 + j];
        __syncthreads();
        for (int k = 2; k <= NF; k <<= 1)
            for (int j = k >> 1; j > 0; j >>= 1) {
                for (int i = tid; i < NF; i += 256) {
                    int ixj = i ^ j;
                    if (ixj > i) {
                        bool up = ((i & k) == 0);
                        float va = s_a[i], vb = s_a[ixj];
                        if ((va > vb) == up) { s_a[i] = vb; s_a[ixj] = va; }
                    }
                }
                __syncthreads();
            }
        float sv[8];
#pragma unroll
        for (int e = 0; e < 8; e++) sv[e] = s_a[tid + e * 256];
        float* src = s_a; float* dst = s_b;
        for (int off = 1; off < NF; off <<= 1) {
            for (int i = tid; i < NF; i += 256)
                dst[i] = src[i] + ((i >= off) ? src[i - off] : 0.0f);
            __syncthreads();
            float* t = src; src = dst; dst = t;
        }
        float kf = 0.0f;
#pragma unroll
        for (int e = 0; e < 8; e++) {
            int i = tid + e * 256;
            if (1.0f + (float)i * sv[e] - src[i] > 0.0f) kf = fmaxf(kf, (float)i);
        }
        kf = block_reduce(kf, rbuf, true);
        int k = (int)kf;
        tau = (src[k] + 1.0f) / (float)k;
        __syncthreads();
    }

    float* om = out + (size_t)row * NF;
    float* op = out + (size_t)NFTOT + (size_t)row * NF;
#pragma unroll
    for (int g = 0; g < 2; g++) {
        const int q = tid + g * 256;
        float m0 = fmaxf(z[g*4+0] - tau, 0.0f);
        float m1 = fmaxf(z[g*4+1] - tau, 0.0f);
        float m2 = fmaxf(z[g*4+2] - tau, 0.0f);
        float m3 = fmaxf(z[g*4+3] - tau, 0.0f);
        ((float4*)om)[q] = make_float4(m0, m1, m2, m3);
        ((float4*)op)[q] = make_float4(pv8[g*4+0] * (GAMMA - m0),
                                       pv8[g*4+1] * (GAMMA - m1),
                                       pv8[g*4+2] * (GAMMA - m2),
                                       pv8[g*4+3] * (GAMMA - m3));
    }
}

// ================================================================
// launch: a, ps, W, b, bn_w, bn_b -> out = concat(m, new_ps)
// ================================================================
extern "C" void kernel_launch(void* const* d_in, const int* in_sizes, int n_in,
                              void* d_out, int out_size) {
    const float* a    = (const float*)d_in[0];
    const float* ps   = (const float*)d_in[1];
    const float* W    = (const float*)d_in[2];
    const float* bn_w = (const float*)d_in[4];
    const float* bn_b = (const float*)d_in[5];
    float* out = (float*)d_out;

    cudaFuncSetAttribute(gemm_hmma_kernel,
                         cudaFuncAttributeMaxDynamicSharedMemorySize,
                         NSTG * STG_BYTES);

    zero_stats_kernel<<<(NF + 255) / 256, 256>>>();
    convA_kernel<<<NROWS * NA / 256, 256>>>(a);
    convW_kernel<<<NF * NA / 256, 256>>>(W);
    gemm_hmma_kernel<<<dim3(NF / 128, NROWS / 128), 256, NSTG * STG_BYTES>>>();
    finalize_kernel<<<NF / 256, 256>>>(bn_w, bn_b);
    row_kernel<<<NROWS, 256>>>(ps, out);
}

// round 7
// speedup vs baseline: 2.4491x; 1.0074x over previous
#include <cuda_runtime.h>
#include <cuda_fp16.h>
#include <math_constants.h>
#include <cstdint>

// Problem constants
#define NROWS 16384
#define NA    256
#define NF    2048
#define NFTOT (NROWS * NF)
#define GAMMA 1.5f
#define BN_EPS 1e-5f

#define BKB   64            // K per pipeline stage
#define NKIT  (NA / BKB)    // 4
#define STG_BYTES 32768     // A 16KB + B 16KB

// ---------------- scratch (allocation-free: __device__ globals) ----------------
__device__ __half g_Xh[NROWS * NF];              // GEMM output (fp16)
__device__ __half g_Ah[(size_t)NROWS * NA];      // fp16(a)
__device__ __half g_Wh[(size_t)NF * NA];         // fp16(W)
__device__ float  g_colsum[NF];
__device__ float  g_colsq[NF];
__device__ float  g_scale[NF];
__device__ float  g_shift[NF];

// ================= PTX helpers (baseline ISA only: valid on sm_103) =================
__device__ __forceinline__ uint32_t smem_u32(const void* p) {
    uint32_t a;
    asm("{ .reg .u64 t; cvta.to.shared.u64 t, %1; cvt.u32.u64 %0, t; }" : "=r"(a) : "l"(p));
    return a;
}
__device__ __forceinline__ void cp16(uint32_t sm, const void* g) {
    asm volatile("cp.async.cg.shared.global [%0], [%1], 16;" :: "r"(sm),
                 "l"(__cvta_generic_to_global(g)));
}
#define CP_COMMIT() asm volatile("cp.async.commit_group;" ::: "memory")
#define CP_WAIT(n)  asm volatile("cp.async.wait_group %0;" :: "n"(n) : "memory")

__device__ __forceinline__ void ldsm_x4(uint32_t& r0, uint32_t& r1, uint32_t& r2,
                                        uint32_t& r3, uint32_t addr) {
    asm volatile("ldmatrix.sync.aligned.m8n8.x4.shared.b16 {%0,%1,%2,%3}, [%4];"
        : "=r"(r0), "=r"(r1), "=r"(r2), "=r"(r3) : "r"(addr));
}
__device__ __forceinline__ void mma16816(float* d, const uint32_t* a,
                                         uint32_t b0, uint32_t b1) {
    asm volatile("mma.sync.aligned.m16n8k16.row.col.f32.f16.f16.f32 "
        "{%0,%1,%2,%3}, {%4,%5,%6,%7}, {%8,%9}, {%0,%1,%2,%3};"
        : "+f"(d[0]), "+f"(d[1]), "+f"(d[2]), "+f"(d[3])
        : "r"(a[0]), "r"(a[1]), "r"(a[2]), "r"(a[3]), "r"(b0), "r"(b1));
}
__device__ __forceinline__ uint32_t h2_bits(__half2 h) {
    union { __half2 h; uint32_t u; } cv;
    cv.h = h;
    return cv.u;
}

// ================================================================
// K1a: fp32 -> fp16 convert of A (vectorized, 4 elems/thread)
// (bias b omitted: cancelled exactly by BatchNorm mean subtraction)
// ================================================================
__global__ void __launch_bounds__(256) convA_kernel(const float* __restrict__ a) {
    int i4 = blockIdx.x * 256 + threadIdx.x;
    float4 v = ((const float4*)a)[i4];
    uint2 o;
    o.x = h2_bits(__floats2half2_rn(v.x, v.y));
    o.y = h2_bits(__floats2half2_rn(v.z, v.w));
    ((uint2*)g_Ah)[i4] = o;
}
// K1b: convert W + zero stats accumulators (merged)
__global__ void __launch_bounds__(256) convW_kernel(const float* __restrict__ W) {
    int i4 = blockIdx.x * 256 + threadIdx.x;
    float4 v = ((const float4*)W)[i4];
    uint2 o;
    o.x = h2_bits(__floats2half2_rn(v.x, v.y));
    o.y = h2_bits(__floats2half2_rn(v.z, v.w));
    ((uint2*)g_Wh)[i4] = o;
    if (blockIdx.x < 8) {
        int f = blockIdx.x * 256 + threadIdx.x;
        g_colsum[f] = 0.0f; g_colsq[f] = 0.0f;
    }
}

// ================================================================
// K2: HMMA GEMM fp16 (mma.sync m16n8k16). CTA 128x128, 4 warps
// (2M x 2N), warp tile 64x64 -> 32 MMAs per 8 ldmatrix per k16.
// BK=64, 3-stage cp.async ring with lookahead 2 (stage (it+2)%3
// never collides with consuming stage it%3; __syncthreads after
// CP_WAIT fences cross-warp reuse).
// smem row = 64 halves = 128B = 8 segs; swizzle seg ^= (row & 7).
// Epilogue: fp16 store to g_Xh + fused column sum/sumsq (fp32).
// ================================================================
__global__ void __launch_bounds__(128, 2)
gemm_hmma_kernel() {
    extern __shared__ char smem[];
    const uint32_t sb = smem_u32(smem);
    const int tid = threadIdx.x;
    const int wid = tid >> 5, lid = tid & 31;
    const int warpM = wid & 1, warpN = wid >> 1;
    const int m0 = blockIdx.y * 128;
    const int f0 = blockIdx.x * 128;

    // ---- hoisted cp.async constants ----
    // thread covers seg s = tid&7 of rows r0 + j*16 (j=0..7) for A and B
    const int s = tid & 7;
    const int r0 = tid >> 3;                       // 0..15
    const uint32_t swc = (uint32_t)((s ^ (r0 & 7)) << 4);   // j*16 keeps r&7
    const uint32_t smA = sb + (uint32_t)r0 * 128u + swc;
    const uint32_t smB = smA + 16384u;
    const char* gA = (const char*)(g_Ah + (size_t)(m0 + r0) * NA) + s * 16;
    const char* gB = (const char*)(g_Wh + (size_t)(f0 + r0) * NA) + s * 16;

    // ---- hoisted ldmatrix bases ----
    uint32_t rbA[4], rbB[4], segoff[4];
#pragma unroll
    for (int t = 0; t < 4; t++) {
        rbA[t] = sb + (uint32_t)(warpM * 64 + t * 16 + (lid & 15)) * 128u;
        rbB[t] = sb + 16384u + (uint32_t)(warpN * 64 + t * 16 + (lid & 15)) * 128u;
    }
#pragma unroll
    for (int ks = 0; ks < 4; ks++)
        segoff[ks] = (uint32_t)(((2 * ks + (lid >> 4)) ^ (lid & 7)) << 4);

    float acc[4][8][4];
#pragma unroll
    for (int t = 0; t < 4; t++)
#pragma unroll
        for (int j = 0; j < 8; j++)
#pragma unroll
            for (int e = 0; e < 4; e++) acc[t][j][e] = 0.0f;

    // prologue: 2 stages in flight (stage p holds iteration p)
#pragma unroll
    for (int p = 0; p < 2; p++) {
        const uint32_t so = p * STG_BYTES;
        const int go = p * 128;                 // 64 halves = 128 bytes
#pragma unroll
        for (int j = 0; j < 8; j++) {
            cp16(smA + so + j * 2048u, gA + (size_t)j * 16 * (NA * 2) + go);
            cp16(smB + so + j * 2048u, gB + (size_t)j * 16 * (NA * 2) + go);
        }
        CP_COMMIT();
    }

#pragma unroll
    for (int it = 0; it < NKIT; it++) {
        CP_WAIT(1);          // stage it%3 complete (<=1 younger group pending)
        __syncthreads();     // also: all warps done reading stage (it+2)%3's old data
        if (it + 2 < NKIT) {
            const uint32_t so = ((it + 2) % 3) * STG_BYTES;
            const int go = (it + 2) * 128;
#pragma unroll
            for (int j = 0; j < 8; j++) {
                cp16(smA + so + j * 2048u, gA + (size_t)j * 16 * (NA * 2) + go);
                cp16(smB + so + j * 2048u, gB + (size_t)j * 16 * (NA * 2) + go);
            }
        }
        CP_COMMIT();

        const uint32_t so = (it % 3) * STG_BYTES;   // compile-time (unrolled)
#pragma unroll
        for (int ks = 0; ks < 4; ks++) {
            uint32_t af[4][4], bf[4][4];
#pragma unroll
            for (int t = 0; t < 4; t++)
                ldsm_x4(af[t][0], af[t][1], af[t][2], af[t][3],
                        rbA[t] + so + segoff[ks]);
#pragma unroll
            for (int u = 0; u < 4; u++)
                ldsm_x4(bf[u][0], bf[u][1], bf[u][2], bf[u][3],
                        rbB[u] + so + segoff[ks]);
#pragma unroll
            for (int t = 0; t < 4; t++)
#pragma unroll
                for (int u = 0; u < 4; u++) {
                    mma16816(acc[t][2 * u],     af[t], bf[u][0], bf[u][2]);
                    mma16816(acc[t][2 * u + 1], af[t], bf[u][1], bf[u][3]);
                }
        }
    }

    // epilogue: C -> g_Xh (half2 stores) + fused column stats (fp32)
#pragma unroll
    for (int t = 0; t < 4; t++) {
        const int rbase = m0 + warpM * 64 + t * 16 + (lid >> 2);
#pragma unroll
        for (int j = 0; j < 8; j++) {
            const int col = f0 + warpN * 64 + j * 8 + (lid & 3) * 2;
            *(__half2*)&g_Xh[(size_t)rbase * NF + col] =
                __floats2half2_rn(acc[t][j][0], acc[t][j][1]);
            *(__half2*)&g_Xh[(size_t)(rbase + 8) * NF + col] =
                __floats2half2_rn(acc[t][j][2], acc[t][j][3]);
        }
    }
    const unsigned FULL = 0xffffffffu;
#pragma unroll
    for (int j = 0; j < 8; j++) {
        float s0 = 0, s1 = 0, q0 = 0, q1 = 0;
#pragma unroll
        for (int t = 0; t < 4; t++) {
            s0 += acc[t][j][0] + acc[t][j][2];
            s1 += acc[t][j][1] + acc[t][j][3];
            q0 += acc[t][j][0]*acc[t][j][0] + acc[t][j][2]*acc[t][j][2];
            q1 += acc[t][j][1]*acc[t][j][1] + acc[t][j][3]*acc[t][j][3];
        }
#pragma unroll
        for (int o = 16; o >= 4; o >>= 1) {
            s0 += __shfl_down_sync(FULL, s0, o);
            s1 += __shfl_down_sync(FULL, s1, o);
            q0 += __shfl_down_sync(FULL, q0, o);
            q1 += __shfl_down_sync(FULL, q1, o);
        }
        if (lid < 4) {
            const int col = f0 + warpN * 64 + j * 8 + lid * 2;
            atomicAdd(&g_colsum[col], s0);
            atomicAdd(&g_colsum[col + 1], s1);
            atomicAdd(&g_colsq[col], q0);
            atomicAdd(&g_colsq[col + 1], q1);
        }
    }
}

// ================================================================
// K3: finalize column stats -> scale/shift
// ================================================================
__global__ void __launch_bounds__(256)
finalize_kernel(const float* __restrict__ bn_w, const float* __restrict__ bn_b) {
    const int f = blockIdx.x * 256 + threadIdx.x;
    const float inv_n = 1.0f / (float)NROWS;
    float mean = g_colsum[f] * inv_n;
    float var  = fmaxf(g_colsq[f] * inv_n - mean * mean, 0.0f);
    float rstd = rsqrtf(var + BN_EPS);
    float sc = bn_w[f] * rstd;
    g_scale[f] = sc;
    g_shift[f] = bn_b[f] - mean * sc;
}

// ================================================================
// K4: per-row sparsemax + outputs (HBM-roofline bound).
// ================================================================
__device__ __forceinline__ float block_reduce(float v, float* buf, bool do_max) {
    const unsigned FULL = 0xffffffffu;
#pragma unroll
    for (int o = 16; o > 0; o >>= 1) {
        float t = __shfl_down_sync(FULL, v, o);
        v = do_max ? fmaxf(v, t) : (v + t);
    }
    const int w = threadIdx.x >> 5, l = threadIdx.x & 31;
    if (l == 0) buf[w] = v;
    __syncthreads();
    if (threadIdx.x < 8) {
        v = buf[threadIdx.x];
#pragma unroll
        for (int o = 4; o > 0; o >>= 1) {
            float t = __shfl_down_sync(0xffu, v, o);
            v = do_max ? fmaxf(v, t) : (v + t);
        }
        if (threadIdx.x == 0) buf[0] = v;
    }
    __syncthreads();
    float r = buf[0];
    __syncthreads();
    return r;
}

__global__ void __launch_bounds__(256)
row_kernel(const float* __restrict__ ps, float* __restrict__ out) {
    __shared__ float s_a[NF];
    __shared__ float s_b[NF];
    __shared__ float rbuf[8];

    const int row = blockIdx.x;
    const int tid = threadIdx.x;
    const int e0 = tid * 8;               // this thread's 8 contiguous elements

    // x: 8 halves = one uint4
    uint4 xr = *(const uint4*)(g_Xh + (size_t)row * NF + e0);
    const float* pp  = ps + (size_t)row * NF + e0;

    float z[8], pv8[8];
    float S = 0.0f, mx = -CUDART_INF_F;

    const uint32_t xw[4] = {xr.x, xr.y, xr.z, xr.w};
#pragma unroll
    for (int g = 0; g < 4; g++) {
        union { uint32_t u; __half2 h; } cv; cv.u = xw[g];
        float2 xv = __half22float2(cv.h);
        float sc0 = g_scale[e0 + 2*g],  sc1 = g_scale[e0 + 2*g + 1];
        float sh0 = g_shift[e0 + 2*g],  sh1 = g_shift[e0 + 2*g + 1];
        float p0 = pp[2*g], p1 = pp[2*g + 1];
        float z0 = fmaf(xv.x, sc0, sh0) * p0;
        float z1 = fmaf(xv.y, sc1, sh1) * p1;
        z[2*g] = z0; z[2*g+1] = z1;
        pv8[2*g] = p0; pv8[2*g+1] = p1;
        S += z0 + z1;
        mx = fmaxf(mx, fmaxf(z0, z1));
    }

    S  = block_reduce(S,  rbuf, false);
    mx = block_reduce(mx, rbuf, true);

    float tau;
    if (1.0f + 2047.0f * mx - S > 0.0f) {
        tau = (S + 1.0f) * (1.0f / 2047.0f);
    } else {
        // exact fallback (ascending bitonic sort + scan) — effectively never taken
#pragma unroll
        for (int j = 0; j < 8; j++) s_a[e0 + j] = z[j];
        __syncthreads();
        for (int k = 2; k <= NF; k <<= 1)
            for (int j = k >> 1; j > 0; j >>= 1) {
                for (int i = tid; i < NF; i += 256) {
                    int ixj = i ^ j;
                    if (ixj > i) {
                        bool up = ((i & k) == 0);
                        float va = s_a[i], vb = s_a[ixj];
                        if ((va > vb) == up) { s_a[i] = vb; s_a[ixj] = va; }
                    }
                }
                __syncthreads();
            }
        float sv[8];
#pragma unroll
        for (int e = 0; e < 8; e++) sv[e] = s_a[tid + e * 256];
        float* src = s_a; float* dst = s_b;
        for (int off = 1; off < NF; off <<= 1) {
            for (int i = tid; i < NF; i += 256)
                dst[i] = src[i] + ((i >= off) ? src[i - off] : 0.0f);
            __syncthreads();
            float* t = src; src = dst; dst = t;
        }
        float kf = 0.0f;
#pragma unroll
        for (int e = 0; e < 8; e++) {
            int i = tid + e * 256;
            if (1.0f + (float)i * sv[e] - src[i] > 0.0f) kf = fmaxf(kf, (float)i);
        }
        kf = block_reduce(kf, rbuf, true);
        int k = (int)kf;
        tau = (src[k] + 1.0f) / (float)k;
        __syncthreads();
    }

    float* om = out + (size_t)row * NF + e0;
    float* op = out + (size_t)NFTOT + (size_t)row * NF + e0;
#pragma unroll
    for (int g = 0; g < 2; g++) {
        float m0 = fmaxf(z[4*g+0] - tau, 0.0f);
        float m1 = fmaxf(z[4*g+1] - tau, 0.0f);
        float m2 = fmaxf(z[4*g+2] - tau, 0.0f);
        float m3 = fmaxf(z[4*g+3] - tau, 0.0f);
        *(float4*)(om + 4*g) = make_float4(m0, m1, m2, m3);
        *(float4*)(op + 4*g) = make_float4(pv8[4*g+0] * (GAMMA - m0),
                                           pv8[4*g+1] * (GAMMA - m1),
                                           pv8[4*g+2] * (GAMMA - m2),
                                           pv8[4*g+3] * (GAMMA - m3));
    }
}

// ================================================================
// launch: a, ps, W, b, bn_w, bn_b -> out = concat(m, new_ps)
// ================================================================
extern "C" void kernel_launch(void* const* d_in, const int* in_sizes, int n_in,
                              void* d_out, int out_size) {
    const float* a    = (const float*)d_in[0];
    const float* ps   = (const float*)d_in[1];
    const float* W    = (const float*)d_in[2];
    const float* bn_w = (const float*)d_in[4];
    const float* bn_b = (const float*)d_in[5];
    float* out = (float*)d_out;

    cudaFuncSetAttribute(gemm_hmma_kernel,
                         cudaFuncAttributeMaxDynamicSharedMemorySize,
                         3 * STG_BYTES);

    convA_kernel<<<NROWS * NA / 1024, 256>>>(a);
    convW_kernel<<<NF * NA / 1024, 256>>>(W);
    gemm_hmma_kernel<<<dim3(NF / 128, NROWS / 128), 128, 3 * STG_BYTES>>>();
    finalize_kernel<<<NF / 256, 256>>>(bn_w, bn_b);
    row_kernel<<<NROWS, 256>>>(ps, out);
}

// round 8
// speedup vs baseline: 3.4358x; 1.4029x over previous
#include <cuda_runtime.h>
#include <cuda_fp16.h>
#include <math_constants.h>
#include <cstdint>

// Problem constants
#define NROWS 16384
#define NA    256
#define NF    2048
#define NFTOT (NROWS * NF)
#define GAMMA 1.5f
#define BN_EPS 1e-5f

#define BKB   64            // K per pipeline stage
#define NKIT  (NA / BKB)    // 4
#define STG_BYTES 32768     // A 16KB + B 16KB

// ---------------- scratch (allocation-free: __device__ globals) ----------------
__device__ __half g_Xh[NROWS * NF];              // GEMM output (fp16)
__device__ __half g_Ah[(size_t)NROWS * NA];      // fp16(a)
__device__ __half g_Wh[(size_t)NF * NA];         // fp16(W)
__device__ float  g_colsum[NF];
__device__ float  g_colsq[NF];

// ================= PTX helpers (baseline ISA only: valid on sm_103) =================
__device__ __forceinline__ uint32_t smem_u32(const void* p) {
    uint32_t a;
    asm("{ .reg .u64 t; cvta.to.shared.u64 t, %1; cvt.u32.u64 %0, t; }" : "=r"(a) : "l"(p));
    return a;
}
__device__ __forceinline__ void cp16(uint32_t sm, const void* g) {
    asm volatile("cp.async.cg.shared.global [%0], [%1], 16;" :: "r"(sm),
                 "l"(__cvta_generic_to_global(g)));
}
#define CP_COMMIT() asm volatile("cp.async.commit_group;" ::: "memory")
#define CP_WAIT(n)  asm volatile("cp.async.wait_group %0;" :: "n"(n) : "memory")

__device__ __forceinline__ void ldsm_x4(uint32_t& r0, uint32_t& r1, uint32_t& r2,
                                        uint32_t& r3, uint32_t addr) {
    asm volatile("ldmatrix.sync.aligned.m8n8.x4.shared.b16 {%0,%1,%2,%3}, [%4];"
        : "=r"(r0), "=r"(r1), "=r"(r2), "=r"(r3) : "r"(addr));
}
__device__ __forceinline__ void mma16816(float* d, const uint32_t* a,
                                         uint32_t b0, uint32_t b1) {
    asm volatile("mma.sync.aligned.m16n8k16.row.col.f32.f16.f16.f32 "
        "{%0,%1,%2,%3}, {%4,%5,%6,%7}, {%8,%9}, {%0,%1,%2,%3};"
        : "+f"(d[0]), "+f"(d[1]), "+f"(d[2]), "+f"(d[3])
        : "r"(a[0]), "r"(a[1]), "r"(a[2]), "r"(a[3]), "r"(b0), "r"(b1));
}
__device__ __forceinline__ uint32_t h2_bits(__half2 h) {
    union { __half2 h; uint32_t u; } cv;
    cv.h = h;
    return cv.u;
}

// ================================================================
// K1a: fp32 -> fp16 convert of A (vectorized, 4 elems/thread)
// (bias b omitted: cancelled exactly by BatchNorm mean subtraction)
// ================================================================
__global__ void __launch_bounds__(256) convA_kernel(const float* __restrict__ a) {
    int i4 = blockIdx.x * 256 + threadIdx.x;
    float4 v = ((const float4*)a)[i4];
    uint2 o;
    o.x = h2_bits(__floats2half2_rn(v.x, v.y));
    o.y = h2_bits(__floats2half2_rn(v.z, v.w));
    ((uint2*)g_Ah)[i4] = o;
}
// K1b: convert W + zero stats accumulators (merged)
__global__ void __launch_bounds__(256) convW_kernel(const float* __restrict__ W) {
    int i4 = blockIdx.x * 256 + threadIdx.x;
    float4 v = ((const float4*)W)[i4];
    uint2 o;
    o.x = h2_bits(__floats2half2_rn(v.x, v.y));
    o.y = h2_bits(__floats2half2_rn(v.z, v.w));
    ((uint2*)g_Wh)[i4] = o;
    if (blockIdx.x < 8) {
        int f = blockIdx.x * 256 + threadIdx.x;
        g_colsum[f] = 0.0f; g_colsq[f] = 0.0f;
    }
}

// ================================================================
// K2: HMMA GEMM fp16 (mma.sync m16n8k16). CTA 128x128, 4 warps
// (2M x 2N), warp tile 64x64. BK=64, 3-stage cp.async ring,
// lookahead 2. (unchanged from Round 7 — passes)
// ================================================================
__global__ void __launch_bounds__(128, 2)
gemm_hmma_kernel() {
    extern __shared__ char smem[];
    const uint32_t sb = smem_u32(smem);
    const int tid = threadIdx.x;
    const int wid = tid >> 5, lid = tid & 31;
    const int warpM = wid & 1, warpN = wid >> 1;
    const int m0 = blockIdx.y * 128;
    const int f0 = blockIdx.x * 128;

    const int s = tid & 7;
    const int r0 = tid >> 3;
    const uint32_t swc = (uint32_t)((s ^ (r0 & 7)) << 4);
    const uint32_t smA = sb + (uint32_t)r0 * 128u + swc;
    const uint32_t smB = smA + 16384u;
    const char* gA = (const char*)(g_Ah + (size_t)(m0 + r0) * NA) + s * 16;
    const char* gB = (const char*)(g_Wh + (size_t)(f0 + r0) * NA) + s * 16;

    uint32_t rbA[4], rbB[4], segoff[4];
#pragma unroll
    for (int t = 0; t < 4; t++) {
        rbA[t] = sb + (uint32_t)(warpM * 64 + t * 16 + (lid & 15)) * 128u;
        rbB[t] = sb + 16384u + (uint32_t)(warpN * 64 + t * 16 + (lid & 15)) * 128u;
    }
#pragma unroll
    for (int ks = 0; ks < 4; ks++)
        segoff[ks] = (uint32_t)(((2 * ks + (lid >> 4)) ^ (lid & 7)) << 4);

    float acc[4][8][4];
#pragma unroll
    for (int t = 0; t < 4; t++)
#pragma unroll
        for (int j = 0; j < 8; j++)
#pragma unroll
            for (int e = 0; e < 4; e++) acc[t][j][e] = 0.0f;

#pragma unroll
    for (int p = 0; p < 2; p++) {
        const uint32_t so = p * STG_BYTES;
        const int go = p * 128;
#pragma unroll
        for (int j = 0; j < 8; j++) {
            cp16(smA + so + j * 2048u, gA + (size_t)j * 16 * (NA * 2) + go);
            cp16(smB + so + j * 2048u, gB + (size_t)j * 16 * (NA * 2) + go);
        }
        CP_COMMIT();
    }

#pragma unroll
    for (int it = 0; it < NKIT; it++) {
        CP_WAIT(1);
        __syncthreads();
        if (it + 2 < NKIT) {
            const uint32_t so = ((it + 2) % 3) * STG_BYTES;
            const int go = (it + 2) * 128;
#pragma unroll
            for (int j = 0; j < 8; j++) {
                cp16(smA + so + j * 2048u, gA + (size_t)j * 16 * (NA * 2) + go);
                cp16(smB + so + j * 2048u, gB + (size_t)j * 16 * (NA * 2) + go);
            }
        }
        CP_COMMIT();

        const uint32_t so = (it % 3) * STG_BYTES;
#pragma unroll
        for (int ks = 0; ks < 4; ks++) {
            uint32_t af[4][4], bf[4][4];
#pragma unroll
            for (int t = 0; t < 4; t++)
                ldsm_x4(af[t][0], af[t][1], af[t][2], af[t][3],
                        rbA[t] + so + segoff[ks]);
#pragma unroll
            for (int u = 0; u < 4; u++)
                ldsm_x4(bf[u][0], bf[u][1], bf[u][2], bf[u][3],
                        rbB[u] + so + segoff[ks]);
#pragma unroll
            for (int t = 0; t < 4; t++)
#pragma unroll
                for (int u = 0; u < 4; u++) {
                    mma16816(acc[t][2 * u],     af[t], bf[u][0], bf[u][2]);
                    mma16816(acc[t][2 * u + 1], af[t], bf[u][1], bf[u][3]);
                }
        }
    }

    // epilogue: C -> g_Xh (half2 stores) + fused column stats (fp32)
#pragma unroll
    for (int t = 0; t < 4; t++) {
        const int rbase = m0 + warpM * 64 + t * 16 + (lid >> 2);
#pragma unroll
        for (int j = 0; j < 8; j++) {
            const int col = f0 + warpN * 64 + j * 8 + (lid & 3) * 2;
            *(__half2*)&g_Xh[(size_t)rbase * NF + col] =
                __floats2half2_rn(acc[t][j][0], acc[t][j][1]);
            *(__half2*)&g_Xh[(size_t)(rbase + 8) * NF + col] =
                __floats2half2_rn(acc[t][j][2], acc[t][j][3]);
        }
    }
    const unsigned FULL = 0xffffffffu;
#pragma unroll
    for (int j = 0; j < 8; j++) {
        float s0 = 0, s1 = 0, q0 = 0, q1 = 0;
#pragma unroll
        for (int t = 0; t < 4; t++) {
            s0 += acc[t][j][0] + acc[t][j][2];
            s1 += acc[t][j][1] + acc[t][j][3];
            q0 += acc[t][j][0]*acc[t][j][0] + acc[t][j][2]*acc[t][j][2];
            q1 += acc[t][j][1]*acc[t][j][1] + acc[t][j][3]*acc[t][j][3];
        }
#pragma unroll
        for (int o = 16; o >= 4; o >>= 1) {
            s0 += __shfl_down_sync(FULL, s0, o);
            s1 += __shfl_down_sync(FULL, s1, o);
            q0 += __shfl_down_sync(FULL, q0, o);
            q1 += __shfl_down_sync(FULL, q1, o);
        }
        if (lid < 4) {
            const int col = f0 + warpN * 64 + j * 8 + lid * 2;
            atomicAdd(&g_colsum[col], s0);
            atomicAdd(&g_colsum[col + 1], s1);
            atomicAdd(&g_colsq[col], q0);
            atomicAdd(&g_colsq[col + 1], q1);
        }
    }
}

// ================================================================
// K4: per-row sparsemax + outputs. Fully coalesced layout
// (q = tid + g*256; 16B-or-8B per lane contiguous). BN scale/shift
// computed inline from column stats (finalize kernel deleted).
// ================================================================
__device__ __forceinline__ float block_reduce(float v, float* buf, bool do_max) {
    const unsigned FULL = 0xffffffffu;
#pragma unroll
    for (int o = 16; o > 0; o >>= 1) {
        float t = __shfl_down_sync(FULL, v, o);
        v = do_max ? fmaxf(v, t) : (v + t);
    }
    const int w = threadIdx.x >> 5, l = threadIdx.x & 31;
    if (l == 0) buf[w] = v;
    __syncthreads();
    if (threadIdx.x < 8) {
        v = buf[threadIdx.x];
#pragma unroll
        for (int o = 4; o > 0; o >>= 1) {
            float t = __shfl_down_sync(0xffu, v, o);
            v = do_max ? fmaxf(v, t) : (v + t);
        }
        if (threadIdx.x == 0) buf[0] = v;
    }
    __syncthreads();
    float r = buf[0];
    __syncthreads();
    return r;
}

__global__ void __launch_bounds__(256)
row_kernel(const float* __restrict__ ps,
           const float* __restrict__ bn_w, const float* __restrict__ bn_b,
           float* __restrict__ out) {
    __shared__ float s_a[NF];
    __shared__ float s_b[NF];
    __shared__ float rbuf[8];

    const int row = blockIdx.x;
    const int tid = threadIdx.x;
    const float inv_n = 1.0f / (float)NROWS;

    const uint2*  xp  = (const uint2*)(g_Xh + (size_t)row * NF);  // 4 halves/lane
    const float4* pp  = (const float4*)(ps  + (size_t)row * NF);
    const float4* csp = (const float4*)g_colsum;
    const float4* cqp = (const float4*)g_colsq;
    const float4* bwp = (const float4*)bn_w;
    const float4* bbp = (const float4*)bn_b;

    float z[8], pv8[8];
    float S = 0.0f, mx = -CUDART_INF_F;

#pragma unroll
    for (int g = 0; g < 2; g++) {
        const int q = tid + g * 256;
        uint2  xv = xp[q];
        float4 pv = pp[q];
        float4 cs = csp[q], cq = cqp[q], bw = bwp[q], bb = bbp[q];

        union { uint32_t u; __half2 h; } c0, c1;
        c0.u = xv.x; c1.u = xv.y;
        float2 x01 = __half22float2(c0.h);
        float2 x23 = __half22float2(c1.h);

        // inline BN finalize: scale = bn_w * rsqrt(var), shift = bn_b - mean*scale
        float mean0 = cs.x * inv_n, mean1 = cs.y * inv_n,
              mean2 = cs.z * inv_n, mean3 = cs.w * inv_n;
        float sc0 = bw.x * rsqrtf(fmaxf(cq.x * inv_n - mean0 * mean0, 0.0f) + BN_EPS);
        float sc1 = bw.y * rsqrtf(fmaxf(cq.y * inv_n - mean1 * mean1, 0.0f) + BN_EPS);
        float sc2 = bw.z * rsqrtf(fmaxf(cq.z * inv_n - mean2 * mean2, 0.0f) + BN_EPS);
        float sc3 = bw.w * rsqrtf(fmaxf(cq.w * inv_n - mean3 * mean3, 0.0f) + BN_EPS);
        float sh0 = bb.x - mean0 * sc0, sh1 = bb.y - mean1 * sc1;
        float sh2 = bb.z - mean2 * sc2, sh3 = bb.w - mean3 * sc3;

        float z0 = fmaf(x01.x, sc0, sh0) * pv.x;
        float z1 = fmaf(x01.y, sc1, sh1) * pv.y;
        float z2 = fmaf(x23.x, sc2, sh2) * pv.z;
        float z3 = fmaf(x23.y, sc3, sh3) * pv.w;
        z[g*4+0]=z0; z[g*4+1]=z1; z[g*4+2]=z2; z[g*4+3]=z3;
        pv8[g*4+0]=pv.x; pv8[g*4+1]=pv.y; pv8[g*4+2]=pv.z; pv8[g*4+3]=pv.w;
        S += (z0 + z1) + (z2 + z3);
        mx = fmaxf(mx, fmaxf(fmaxf(z0, z1), fmaxf(z2, z3)));
    }

    S  = block_reduce(S,  rbuf, false);
    mx = block_reduce(mx, rbuf, true);

    float tau;
    if (1.0f + 2047.0f * mx - S > 0.0f) {
        tau = (S + 1.0f) * (1.0f / 2047.0f);
    } else {
        // exact fallback (ascending bitonic sort + scan) — effectively never taken
#pragma unroll
        for (int g = 0; g < 2; g++)
#pragma unroll
            for (int j = 0; j < 4; j++)
                s_a[(tid + g * 256) * 4 + j] = z[g * 4 + j];
        __syncthreads();
        for (int k = 2; k <= NF; k <<= 1)
            for (int j = k >> 1; j > 0; j >>= 1) {
                for (int i = tid; i < NF; i += 256) {
                    int ixj = i ^ j;
                    if (ixj > i) {
                        bool up = ((i & k) == 0);
                        float va = s_a[i], vb = s_a[ixj];
                        if ((va > vb) == up) { s_a[i] = vb; s_a[ixj] = va; }
                    }
                }
                __syncthreads();
            }
        float sv[8];
#pragma unroll
        for (int e = 0; e < 8; e++) sv[e] = s_a[tid + e * 256];
        float* src = s_a; float* dst = s_b;
        for (int off = 1; off < NF; off <<= 1) {
            for (int i = tid; i < NF; i += 256)
                dst[i] = src[i] + ((i >= off) ? src[i - off] : 0.0f);
            __syncthreads();
            float* t = src; src = dst; dst = t;
        }
        float kf = 0.0f;
#pragma unroll
        for (int e = 0; e < 8; e++) {
            int i = tid + e * 256;
            if (1.0f + (float)i * sv[e] - src[i] > 0.0f) kf = fmaxf(kf, (float)i);
        }
        kf = block_reduce(kf, rbuf, true);
        int k = (int)kf;
        tau = (src[k] + 1.0f) / (float)k;
        __syncthreads();
    }

    float* om = out + (size_t)row * NF;
    float* op = out + (size_t)NFTOT + (size_t)row * NF;
#pragma unroll
    for (int g = 0; g < 2; g++) {
        const int q = tid + g * 256;
        float m0 = fmaxf(z[g*4+0] - tau, 0.0f);
        float m1 = fmaxf(z[g*4+1] - tau, 0.0f);
        float m2 = fmaxf(z[g*4+2] - tau, 0.0f);
        float m3 = fmaxf(z[g*4+3] - tau, 0.0f);
        ((float4*)om)[q] = make_float4(m0, m1, m2, m3);
        ((float4*)op)[q] = make_float4(pv8[g*4+0] * (GAMMA - m0),
                                       pv8[g*4+1] * (GAMMA - m1),
                                       pv8[g*4+2] * (GAMMA - m2),
                                       pv8[g*4+3] * (GAMMA - m3));
    }
}

// ================================================================
// launch: a, ps, W, b, bn_w, bn_b -> out = concat(m, new_ps)
// ================================================================
extern "C" void kernel_launch(void* const* d_in, const int* in_sizes, int n_in,
                              void* d_out, int out_size) {
    const float* a    = (const float*)d_in[0];
    const float* ps   = (const float*)d_in[1];
    const float* W    = (const float*)d_in[2];
    const float* bn_w = (const float*)d_in[4];
    const float* bn_b = (const float*)d_in[5];
    float* out = (float*)d_out;

    cudaFuncSetAttribute(gemm_hmma_kernel,
                         cudaFuncAttributeMaxDynamicSharedMemorySize,
                         3 * STG_BYTES);

    convA_kernel<<<NROWS * NA / 1024, 256>>>(a);
    convW_kernel<<<NF * NA / 1024, 256>>>(W);
    gemm_hmma_kernel<<<dim3(NF / 128, NROWS / 128), 128, 3 * STG_BYTES>>>();
    row_kernel<<<NROWS, 256>>>(ps, bn_w, bn_b, out);
}